// round 4
// baseline (speedup 1.0000x reference)
#include <cuda_runtime.h>

#define N_FEAT 512
#define FDIM   768
#define HID    256
#define NPAIRS 130816   // 512*511/2

// Scratch: [512][512]; cols 0..255 = A_i = E_i@W1_top + b1 ; cols 256..511 = B_i = E_i@W1_bot
__device__ float g_AB[N_FEAT * 512];

// ---------------------------------------------------------------------------
// Kernel 1: C[512,512] = E[512,768] @ [W1_top | W1_bot] (+ b1 on first 256 cols)
// BM=32, BN=64, BK=16, 128 threads, 4x4 microtile -> grid (8,16) = 128 blocks
// ---------------------------------------------------------------------------
#define BM 32
#define BN 64
#define BK 16

__global__ __launch_bounds__(128) void gemm_kernel(const float* __restrict__ E,
                                                   const float* __restrict__ W1,
                                                   const float* __restrict__ b1) {
    __shared__ float Es[BK][BM + 4];   // [16][36] : +4 pad
    __shared__ float Ws[BK][BN];       // [16][64]

    const int tid  = threadIdx.x;
    const int txx  = tid & 15;         // col group 0..15  -> cols txx*4..+3
    const int tyy  = tid >> 4;         // row group 0..7   -> rows tyy*4..+3
    const int row0 = blockIdx.y * BM;
    const int col0 = blockIdx.x * BN;

    float acc[4][4] = {};

    for (int k0 = 0; k0 < FDIM; k0 += BK) {
        // Load Es[kk][r] = E[row0+r][k0+kk]  (coalesced along kk)
        {
            const int kk = tid & 15;
            const int rb = tid >> 4;
            #pragma unroll
            for (int p = 0; p < 4; p++) {
                const int r = rb + p * 8;
                Es[kk][r] = E[(row0 + r) * FDIM + (k0 + kk)];
            }
        }
        // Load Ws[kk][n] = W row (k0+kk) of the combined [W1_top | W1_bot]
        #pragma unroll
        for (int p = 0; p < 8; p++) {
            const int idx = p * 128 + tid;
            const int kk  = idx >> 6;
            const int n   = idx & 63;
            const int c   = col0 + n;
            Ws[kk][n] = (c < HID) ? W1[(k0 + kk) * HID + c]
                                  : W1[(FDIM + k0 + kk) * HID + (c - HID)];
        }
        __syncthreads();

        #pragma unroll
        for (int kk = 0; kk < BK; kk++) {
            const float4 a = *(const float4*)&Es[kk][tyy * 4];
            const float4 b = *(const float4*)&Ws[kk][txx * 4];
            const float av[4] = {a.x, a.y, a.z, a.w};
            const float bv[4] = {b.x, b.y, b.z, b.w};
            #pragma unroll
            for (int m = 0; m < 4; m++)
                #pragma unroll
                for (int n = 0; n < 4; n++)
                    acc[m][n] = fmaf(av[m], bv[n], acc[m][n]);
        }
        __syncthreads();
    }

    // Epilogue: add b1 on the A half, store float4 per row
    const int cbase = col0 + txx * 4;
    float bias[4];
    #pragma unroll
    for (int n = 0; n < 4; n++) {
        const int c = cbase + n;
        bias[n] = (c < HID) ? b1[c] : 0.0f;
    }
    #pragma unroll
    for (int m = 0; m < 4; m++) {
        const int r = row0 + tyy * 4 + m;
        float4 v;
        v.x = acc[m][0] + bias[0];
        v.y = acc[m][1] + bias[1];
        v.z = acc[m][2] + bias[2];
        v.w = acc[m][3] + bias[3];
        *(float4*)&g_AB[r * 512 + cbase] = v;
    }
}

// ---------------------------------------------------------------------------
// Kernel 2: scores. 136 triangular 32x32 tiles (ti<=tj), one block each.
// lane = local j, warp w handles local i rows w*4..w*4+3. No warp reduce;
// coalesced stores. sB rows padded to 260 floats: stride % 32 == 4 -> each
// 8-lane LDS.128 phase covers all 32 banks exactly once (conflict-free).
// ---------------------------------------------------------------------------
#define SB_STRIDE 260
#define NTILES 16          // 512/32
#define NTRI   136         // 16*17/2

__global__ __launch_bounds__(256) void pair_kernel(const float* __restrict__ W2,
                                                   const float* __restrict__ B2,
                                                   float* __restrict__ out,
                                                   int write_idx) {
    // linear blockIdx.x -> (ti, tj) with ti <= tj, row-major over triangle
    const int b = blockIdx.x;
    int ti = 0, rem = b;
    #pragma unroll 1
    while (rem >= NTILES - ti) { rem -= NTILES - ti; ti++; }
    const int tj = ti + rem;

    extern __shared__ float sm[];
    float* sA  = sm;                          // 32 rows * 256
    float* sB  = sm + 32 * 256;               // 32 rows * 260 (padded)
    float* sW2 = sB + 32 * SB_STRIDE;         // 256

    const int tid = threadIdx.x;

    if (tid < 64)
        *(float4*)&sW2[tid * 4] = *(const float4*)&W2[tid * 4];

    // Stage A and B tiles
    #pragma unroll
    for (int p = 0; p < 8; p++) {
        const int idx = p * 256 + tid;   // float4 index, 2048 total
        const int r   = idx >> 6;
        const int c4  = idx & 63;
        const float4 va = *(const float4*)&g_AB[(ti * 32 + r) * 512 + c4 * 4];
        *(float4*)&sA[r * 256 + c4 * 4] = va;
        const float4 vb = *(const float4*)&g_AB[(tj * 32 + r) * 512 + 256 + c4 * 4];
        *(float4*)&sB[r * SB_STRIDE + c4 * 4] = vb;
    }
    __syncthreads();

    const int w    = tid >> 5;      // warp 0..7
    const int lane = tid & 31;      // local j
    const float b2v = B2[0];

    float acc[4] = {0.f, 0.f, 0.f, 0.f};
    const float* bRow  = &sB[lane * SB_STRIDE];
    const float* aBase = &sA[(w * 4) * 256];

    #pragma unroll 4
    for (int c4 = 0; c4 < 64; c4++) {
        const float4 bv = *(const float4*)&bRow[c4 * 4];
        const float4 wv = *(const float4*)&sW2[c4 * 4];
        #pragma unroll
        for (int s = 0; s < 4; s++) {
            const float4 a = *(const float4*)&aBase[s * 256 + c4 * 4];
            float h;
            h = fmaxf(a.x + bv.x, 0.f); acc[s] = fmaf(h, wv.x, acc[s]);
            h = fmaxf(a.y + bv.y, 0.f); acc[s] = fmaf(h, wv.y, acc[s]);
            h = fmaxf(a.z + bv.z, 0.f); acc[s] = fmaf(h, wv.z, acc[s]);
            h = fmaxf(a.w + bv.w, 0.f); acc[s] = fmaf(h, wv.w, acc[s]);
        }
    }

    const int j = tj * 32 + lane;
    #pragma unroll
    for (int s = 0; s < 4; s++) {
        const int li = w * 4 + s;
        const int i  = ti * 32 + li;
        if (ti != tj || lane > li) {
            // row-major (i<j) enumeration index, matches jnp.triu_indices(n, k=1)
            const int p = i * N_FEAT - (i * (i + 1)) / 2 + (j - i - 1);
            const float sc = acc[s] + b2v;
            if (write_idx) {
                out[p]              = (float)i;
                out[NPAIRS + p]     = (float)j;
                out[2 * NPAIRS + p] = sc;
            } else {
                out[p] = sc;
            }
        }
    }
}

// ---------------------------------------------------------------------------

extern "C" void kernel_launch(void* const* d_in, const int* in_sizes, int n_in,
                              void* d_out, int out_size) {
    const float* E  = (const float*)d_in[0];
    const float* W1 = (const float*)d_in[1];
    const float* b1 = (const float*)d_in[2];
    const float* W2 = (const float*)d_in[3];
    const float* b2 = (const float*)d_in[4];
    float* out = (float*)d_out;

    dim3 ggrid(512 / BN, 512 / BM);   // (8,16) = 128 blocks
    gemm_kernel<<<ggrid, 128>>>(E, W1, b1);

    const int write_idx = (out_size >= 3 * NPAIRS) ? 1 : 0;
    const size_t smem = (size_t)(32 * 256 + 32 * SB_STRIDE + 256) * sizeof(float); // 67072 B
    cudaFuncSetAttribute(pair_kernel, cudaFuncAttributeMaxDynamicSharedMemorySize, (int)smem);
    pair_kernel<<<NTRI, 256, smem>>>(W2, b2, out, write_idx);
}

// round 5
// speedup vs baseline: 1.2591x; 1.2591x over previous
#include <cuda_runtime.h>

#define N_FEAT 512
#define FDIM   768
#define HID    256
#define NPAIRS 130816   // 512*511/2
#define KSPLIT 2
#define KHALF  (FDIM / KSPLIT)   // 384

// Scratch: [2][512][512] split-K partials.
// cols 0..255 = A_i partial (b1 folded into slice 0) ; cols 256..511 = B_i partial
__device__ float g_AB[KSPLIT * N_FEAT * 512];

// ---------------------------------------------------------------------------
// Kernel 1: C[512,512] = E[512,768] @ [W1_top | W1_bot] (+ b1 on first 256 cols)
// BM=32, BN=64, BK=16, 128 threads, 4x4 microtile, split-K x2
// grid (8,16,2) = 256 blocks -> ~2 blocks/SM (8 warps), LDG prefetched to regs.
// ---------------------------------------------------------------------------
#define BM 32
#define BN 64
#define BK 16
#define NT_K (KHALF / BK)   // 24 tiles per block

__global__ __launch_bounds__(128) void gemm_kernel(const float* __restrict__ E,
                                                   const float* __restrict__ W1,
                                                   const float* __restrict__ b1) {
    __shared__ float Es[BK][BM + 4];   // [16][36]
    __shared__ float Ws[BK][BN];       // [16][64]

    const int tid  = threadIdx.x;
    const int txx  = tid & 15;         // col group 0..15 -> cols txx*4..+3
    const int tyy  = tid >> 4;         // row group 0..7  -> rows tyy*4..+3
    const int row0 = blockIdx.y * BM;
    const int col0 = blockIdx.x * BN;
    const int kz   = blockIdx.z;
    const int kb   = kz * KHALF;

    // loader coords
    const int kkL = tid & 15;
    const int rbL = tid >> 4;

    float acc[4][4] = {};
    float eR[4];
    float wR[8];

    // Prologue: prefetch tile 0 into registers
    #pragma unroll
    for (int p = 0; p < 4; p++)
        eR[p] = E[(row0 + rbL + p * 8) * FDIM + kb + kkL];
    #pragma unroll
    for (int p = 0; p < 8; p++) {
        const int idx = p * 128 + tid;
        const int kk  = idx >> 6;
        const int n   = idx & 63;
        const int c   = col0 + n;
        wR[p] = (c < HID) ? W1[(kb + kk) * HID + c]
                          : W1[(FDIM + kb + kk) * HID + (c - HID)];
    }

    for (int t = 0; t < NT_K; t++) {
        // Commit prefetched regs to smem
        #pragma unroll
        for (int p = 0; p < 4; p++)
            Es[kkL][rbL + p * 8] = eR[p];
        #pragma unroll
        for (int p = 0; p < 8; p++) {
            const int idx = p * 128 + tid;
            Ws[idx >> 6][idx & 63] = wR[p];
        }
        __syncthreads();

        // Prefetch next tile (LDG latency hidden behind compute below)
        if (t < NT_K - 1) {
            const int kn = kb + (t + 1) * BK;
            #pragma unroll
            for (int p = 0; p < 4; p++)
                eR[p] = E[(row0 + rbL + p * 8) * FDIM + kn + kkL];
            #pragma unroll
            for (int p = 0; p < 8; p++) {
                const int idx = p * 128 + tid;
                const int kk  = idx >> 6;
                const int n   = idx & 63;
                const int c   = col0 + n;
                wR[p] = (c < HID) ? W1[(kn + kk) * HID + c]
                                  : W1[(FDIM + kn + kk) * HID + (c - HID)];
            }
        }

        // Compute
        #pragma unroll
        for (int kk = 0; kk < BK; kk++) {
            const float4 a = *(const float4*)&Es[kk][tyy * 4];
            const float4 b = *(const float4*)&Ws[kk][txx * 4];
            const float av[4] = {a.x, a.y, a.z, a.w};
            const float bv[4] = {b.x, b.y, b.z, b.w};
            #pragma unroll
            for (int m = 0; m < 4; m++)
                #pragma unroll
                for (int n = 0; n < 4; n++)
                    acc[m][n] = fmaf(av[m], bv[n], acc[m][n]);
        }
        __syncthreads();
    }

    // Epilogue: fold b1 into slice 0 only
    const int cbase = col0 + txx * 4;
    float bias[4];
    #pragma unroll
    for (int n = 0; n < 4; n++) {
        const int c = cbase + n;
        bias[n] = (kz == 0 && c < HID) ? b1[c] : 0.0f;
    }
    float* dst = g_AB + kz * (N_FEAT * 512);
    #pragma unroll
    for (int m = 0; m < 4; m++) {
        const int r = row0 + tyy * 4 + m;
        float4 v;
        v.x = acc[m][0] + bias[0];
        v.y = acc[m][1] + bias[1];
        v.z = acc[m][2] + bias[2];
        v.w = acc[m][3] + bias[3];
        *(float4*)&dst[r * 512 + cbase] = v;
    }
}

// ---------------------------------------------------------------------------
// Kernel 2: scores. 136 triangular 32x32 tiles (ti<=tj), one block each,
// 512 threads (16 warps/SM). lane = local j, warp w handles rows w*2, w*2+1.
// Staging sums the two split-K partials. sB stride 260 -> conflict-free.
// ---------------------------------------------------------------------------
#define SB_STRIDE 260
#define NTILES 16          // 512/32
#define NTRI   136         // 16*17/2
#define KOFF   (N_FEAT * 512)

__global__ __launch_bounds__(512) void pair_kernel(const float* __restrict__ W2,
                                                   const float* __restrict__ B2,
                                                   float* __restrict__ out,
                                                   int write_idx) {
    // linear blockIdx.x -> (ti, tj) with ti <= tj
    const int b = blockIdx.x;
    int ti = 0, rem = b;
    #pragma unroll 1
    while (rem >= NTILES - ti) { rem -= NTILES - ti; ti++; }
    const int tj = ti + rem;

    extern __shared__ float sm[];
    float* sA  = sm;                          // 32 rows * 256
    float* sB  = sm + 32 * 256;               // 32 rows * 260 (padded)
    float* sW2 = sB + 32 * SB_STRIDE;         // 256

    const int tid = threadIdx.x;

    if (tid < 64)
        *(float4*)&sW2[tid * 4] = *(const float4*)&W2[tid * 4];

    // Stage A and B tiles (sum the split-K partials)
    #pragma unroll
    for (int p = 0; p < 4; p++) {
        const int idx = p * 512 + tid;   // float4 index, 2048 total
        const int r   = idx >> 6;
        const int c4  = idx & 63;
        const int offA = (ti * 32 + r) * 512 + c4 * 4;
        const float4 a0 = *(const float4*)&g_AB[offA];
        const float4 a1 = *(const float4*)&g_AB[KOFF + offA];
        float4 va; va.x = a0.x + a1.x; va.y = a0.y + a1.y;
                   va.z = a0.z + a1.z; va.w = a0.w + a1.w;
        *(float4*)&sA[r * 256 + c4 * 4] = va;
        const int offB = (tj * 32 + r) * 512 + 256 + c4 * 4;
        const float4 b0 = *(const float4*)&g_AB[offB];
        const float4 b1v = *(const float4*)&g_AB[KOFF + offB];
        float4 vb; vb.x = b0.x + b1v.x; vb.y = b0.y + b1v.y;
                   vb.z = b0.z + b1v.z; vb.w = b0.w + b1v.w;
        *(float4*)&sB[r * SB_STRIDE + c4 * 4] = vb;
    }
    __syncthreads();

    const int w    = tid >> 5;      // warp 0..15
    const int lane = tid & 31;      // local j
    const float b2v = B2[0];

    float acc[2] = {0.f, 0.f};
    const float* bRow  = &sB[lane * SB_STRIDE];
    const float* aBase = &sA[(w * 2) * 256];

    #pragma unroll 4
    for (int c4 = 0; c4 < 64; c4++) {
        const float4 bv = *(const float4*)&bRow[c4 * 4];
        const float4 wv = *(const float4*)&sW2[c4 * 4];
        #pragma unroll
        for (int s = 0; s < 2; s++) {
            const float4 a = *(const float4*)&aBase[s * 256 + c4 * 4];
            float h;
            h = fmaxf(a.x + bv.x, 0.f); acc[s] = fmaf(h, wv.x, acc[s]);
            h = fmaxf(a.y + bv.y, 0.f); acc[s] = fmaf(h, wv.y, acc[s]);
            h = fmaxf(a.z + bv.z, 0.f); acc[s] = fmaf(h, wv.z, acc[s]);
            h = fmaxf(a.w + bv.w, 0.f); acc[s] = fmaf(h, wv.w, acc[s]);
        }
    }

    const int j = tj * 32 + lane;
    #pragma unroll
    for (int s = 0; s < 2; s++) {
        const int li = w * 2 + s;
        const int i  = ti * 32 + li;
        if (ti != tj || lane > li) {
            // row-major (i<j) enumeration index, matches jnp.triu_indices(n, k=1)
            const int p = i * N_FEAT - (i * (i + 1)) / 2 + (j - i - 1);
            const float sc = acc[s] + b2v;
            if (write_idx) {
                out[p]              = (float)i;
                out[NPAIRS + p]     = (float)j;
                out[2 * NPAIRS + p] = sc;
            } else {
                out[p] = sc;
            }
        }
    }
}

// ---------------------------------------------------------------------------

extern "C" void kernel_launch(void* const* d_in, const int* in_sizes, int n_in,
                              void* d_out, int out_size) {
    const float* E  = (const float*)d_in[0];
    const float* W1 = (const float*)d_in[1];
    const float* b1 = (const float*)d_in[2];
    const float* W2 = (const float*)d_in[3];
    const float* b2 = (const float*)d_in[4];
    float* out = (float*)d_out;

    dim3 ggrid(512 / BN, 512 / BM, KSPLIT);   // (8,16,2) = 256 blocks
    gemm_kernel<<<ggrid, 128>>>(E, W1, b1);

    const int write_idx = (out_size >= 3 * NPAIRS) ? 1 : 0;
    const size_t smem = (size_t)(32 * 256 + 32 * SB_STRIDE + 256) * sizeof(float); // 67072 B
    cudaFuncSetAttribute(pair_kernel, cudaFuncAttributeMaxDynamicSharedMemorySize, (int)smem);
    pair_kernel<<<NTRI, 512, smem>>>(W2, b2, out, write_idx);
}